// round 12
// baseline (speedup 1.0000x reference)
#include <cuda_runtime.h>
#include <cuda_bf16.h>
#include <cstdint>

#define N_ROWS 8192
#define DIM    128
#define NCLS   64
#define TI     128                 // CTA tile (M = N = 128)
#define NBI    (N_ROWS / TI)       // 64
#define NT     (NBI * 2)           // 128 partial slots per row
#define NTILES (NBI * (NBI + 1) / 2)   // 2080 upper-tri tiles
#define GRID_P 296                 // persistent CTAs (148 SMs x 2)
#define SROW   136                 // padded smem row stride (bf16 elems) = 272 B
#define CPAD   33                  // scol contributor stride (pad vs 32)
#define RBLK   512                 // k_row blocks

// ---- scratch (__device__ globals; no cudaMalloc allowed) ----
__device__ __nv_bfloat16 g_xb[N_ROWS * DIM];       // normalized*sqrt(EXSCALE), bf16
__device__ float g_negp[(size_t)N_ROWS * NT];      // [row][slot]
__device__ float g_posp[(size_t)N_ROWS * NT];
__device__ int   g_cnt[NCLS];
__device__ float g_bsum[RBLK];
__device__ int   g_done;                           // zero-init; reset each call

#define EXSCALE  2.8853900817779268f   // log2(e)/T, T=0.5
#define SQRT_EXS 1.6986436490789138f   // sqrt(EXSCALE)

__device__ __forceinline__ uint32_t smem_u32(const void* p) {
    uint32_t a;
    asm("{ .reg .u64 t; cvta.to.shared.u64 t, %1; cvt.u32.u64 %0, t; }" : "=r"(a) : "l"(p));
    return a;
}
__device__ __forceinline__ float ex2f(float x) {
    float r; asm("ex2.approx.f32 %0, %1;" : "=f"(r) : "f"(x)); return r;
}
__device__ __forceinline__ void ldsm4(uint32_t* r, uint32_t addr) {
    asm volatile("ldmatrix.sync.aligned.m8n8.x4.shared.b16 {%0,%1,%2,%3}, [%4];"
                 : "=r"(r[0]), "=r"(r[1]), "=r"(r[2]), "=r"(r[3]) : "r"(addr));
}
__device__ __forceinline__ void mma16816(float* d, const uint32_t* a,
                                         uint32_t b0, uint32_t b1) {
    asm volatile(
        "mma.sync.aligned.m16n8k16.row.col.f32.bf16.bf16.f32 "
        "{%0,%1,%2,%3}, {%4,%5,%6,%7}, {%8,%9}, {%0,%1,%2,%3};"
        : "+f"(d[0]), "+f"(d[1]), "+f"(d[2]), "+f"(d[3])
        : "r"(a[0]), "r"(a[1]), "r"(a[2]), "r"(a[3]), "r"(b0), "r"(b1));
}

__global__ void k_init() {
    if (threadIdx.x < NCLS) g_cnt[threadIdx.x] = 0;
}

// One warp per row: float4 loads, shfl reduce, bf16x4 store.
// Label histogram via integer global atomics (deterministic).
__global__ void k_norm(const float* __restrict__ x,
                       const int* __restrict__ lab) {
    int wid  = (blockIdx.x * 256 + threadIdx.x) >> 5;   // global warp = row
    int lane = threadIdx.x & 31;
    float4 v = *(const float4*)&x[(size_t)wid * DIM + lane * 4];
    float ss = v.x * v.x + v.y * v.y + v.z * v.z + v.w * v.w;
    #pragma unroll
    for (int o = 16; o > 0; o >>= 1) ss += __shfl_xor_sync(0xffffffffu, ss, o);
    float sc = SQRT_EXS / fmaxf(sqrtf(ss), 1e-12f);
    __nv_bfloat162 lo = {__float2bfloat16(v.x * sc), __float2bfloat16(v.y * sc)};
    __nv_bfloat162 hi = {__float2bfloat16(v.z * sc), __float2bfloat16(v.w * sc)};
    *(__nv_bfloat162*)&g_xb[(size_t)wid * DIM + lane * 4]     = lo;
    *(__nv_bfloat162*)&g_xb[(size_t)wid * DIM + lane * 4 + 2] = hi;
    if (lane == 0) atomicAdd(&g_cnt[lab[wid] & (NCLS - 1)], 1);
}

// Persistent upper-triangular Gram: 296 CTAs loop over 2080 tiles.
// Row-side partials (slots 2*bj+warp_n) + column-side (slots 2*bi+{0,1}).
__global__ void __launch_bounds__(256, 2)
k_pair(const int* __restrict__ lab) {
    extern __shared__ char sm[];
    __nv_bfloat16* As = (__nv_bfloat16*)sm;            // [128][SROW]
    __nv_bfloat16* Bs = As + TI * SROW;                // [128][SROW]
    int* labJ = (int*)(Bs + TI * SROW);                // [128]
    int* labI = labJ + TI;                             // [128]
    float* scol = (float*)sm;                          // reused post-MMA: [2][128][CPAD]

    int tid  = threadIdx.x;
    int w    = tid >> 5;
    int lane = tid & 31;
    int warp_m = w >> 1;                    // 0..3  -> 32-row slab
    int warp_n = w & 1;                     // 0..1  -> 64-col half
    uint32_t asb = smem_u32(As), bsb = smem_u32(Bs);

    uint32_t a_row = (uint32_t)(warp_m * 32 + (lane & 7) + ((lane >> 3) & 1) * 8);
    uint32_t a_k   = (uint32_t)((lane >> 4) * 8);
    uint32_t aaddr = asb + a_row * (SROW * 2) + a_k * 2;
    uint32_t b_n = (uint32_t)(warp_n * 64 + ((lane >> 4) << 3) + (lane & 7));
    uint32_t b_k = (uint32_t)(((lane >> 3) & 1) * 8);
    uint32_t baddr = bsb + b_n * (SROW * 2) + b_k * 2;

    for (int t4 = blockIdx.x; t4 < NTILES; t4 += GRID_P) {
        // Triangular decode: t = bj*(bj+1)/2 + bi, bi <= bj.
        int bj = (int)((sqrt(8.0 * (double)t4 + 1.0) - 1.0) * 0.5);
        int bi = t4 - bj * (bj + 1) / 2;
        int i0 = bi * TI;
        int j0 = bj * TI;

        __syncthreads();     // smem (scol of prev iter) free before reuse

        #pragma unroll
        for (int it = 0; it < 16; it++) {
            int idx = tid + it * 256;           // 0..4095
            int sub = idx >> 11;                // 0 = A(i), 1 = B(j)
            int loc = idx & 2047;
            int row = loc >> 4, c = loc & 15;
            int grow = (sub ? j0 : i0) + row;
            uint4 v = *(const uint4*)((const char*)g_xb + ((size_t)grow * DIM + c * 8) * 2);
            __nv_bfloat16* dst = sub ? Bs : As;
            *(uint4*)((char*)dst + row * (SROW * 2) + c * 16) = v;
        }
        if (tid < TI) labJ[tid] = lab[j0 + tid];
        else          labI[tid - TI] = lab[i0 + tid - TI];
        __syncthreads();

        float acc[2][8][4];
        #pragma unroll
        for (int mf = 0; mf < 2; mf++)
            #pragma unroll
            for (int nf = 0; nf < 8; nf++)
                #pragma unroll
                for (int e = 0; e < 4; e++) acc[mf][nf][e] = 0.0f;

        #pragma unroll
        for (int ks = 0; ks < 8; ks++) {
            uint32_t a[2][4], b[4][4];
            ldsm4(a[0], aaddr + ks * 32);
            ldsm4(a[1], aaddr + 16 * (SROW * 2) + ks * 32);
            #pragma unroll
            for (int q = 0; q < 4; q++)
                ldsm4(b[q], baddr + q * 16 * (SROW * 2) + ks * 32);
            #pragma unroll
            for (int mf = 0; mf < 2; mf++)
                #pragma unroll
                for (int nf = 0; nf < 8; nf++)
                    mma16816(acc[mf][nf], a[mf], b[nf >> 1][(nf & 1) * 2],
                             b[nf >> 1][(nf & 1) * 2 + 1]);
        }

        int lj[8][2];
        #pragma unroll
        for (int nf = 0; nf < 8; nf++) {
            int j = warp_n * 64 + nf * 8 + ((lane & 3) << 1);
            lj[nf][0] = labJ[j];
            lj[nf][1] = labJ[j + 1];
        }
        int li4[2][2];
        #pragma unroll
        for (int mf = 0; mf < 2; mf++)
            #pragma unroll
            for (int rh = 0; rh < 2; rh++)
                li4[mf][rh] = labI[warp_m * 32 + mf * 16 + (lane >> 2) + rh * 8];
        __syncthreads();   // labels consumed; smem reused as scol

        float colneg[8][2], colpos[8][2];
        #pragma unroll
        for (int nf = 0; nf < 8; nf++)
            colneg[nf][0] = colneg[nf][1] = colpos[nf][0] = colpos[nf][1] = 0.0f;

        #pragma unroll
        for (int mf = 0; mf < 2; mf++) {
            #pragma unroll
            for (int rh = 0; rh < 2; rh++) {
                int li = li4[mf][rh];
                float neg = 0.0f, pos = 0.0f;
                #pragma unroll
                for (int nf = 0; nf < 8; nf++) {
                    float s0 = ex2f(acc[mf][nf][2 * rh]);
                    float s1 = ex2f(acc[mf][nf][2 * rh + 1]);
                    neg += s0 + s1;
                    colneg[nf][0] += s0;
                    colneg[nf][1] += s1;
                    if (li == lj[nf][0]) { pos += s0; colpos[nf][0] += s0; }
                    if (li == lj[nf][1]) { pos += s1; colpos[nf][1] += s1; }
                }
                neg += __shfl_xor_sync(0xffffffffu, neg, 1);
                neg += __shfl_xor_sync(0xffffffffu, neg, 2);
                pos += __shfl_xor_sync(0xffffffffu, pos, 1);
                pos += __shfl_xor_sync(0xffffffffu, pos, 2);
                if ((lane & 3) == 0) {
                    int grow = i0 + warp_m * 32 + mf * 16 + (lane >> 2) + rh * 8;
                    g_negp[(size_t)grow * NT + 2 * bj + warp_n] = neg;
                    g_posp[(size_t)grow * NT + 2 * bj + warp_n] = pos;
                }
            }
        }

        // Column-side smem transpose-reduce.
        {
            int contrib = warp_m * 8 + (lane >> 2);
            #pragma unroll
            for (int nf = 0; nf < 8; nf++) {
                int col = warp_n * 64 + nf * 8 + ((lane & 3) << 1);
                scol[(col)           * CPAD + contrib] = colneg[nf][0];
                scol[(col + 1)       * CPAD + contrib] = colneg[nf][1];
                scol[(128 + col)     * CPAD + contrib] = colpos[nf][0];
                scol[(128 + col + 1) * CPAD + contrib] = colpos[nf][1];
            }
        }
        __syncthreads();

        if (bi != bj) {
            int col = tid & 127, arr = tid >> 7;   // 0 = neg, 1 = pos
            const float* s = scol + (arr * 128 + col) * CPAD;
            float v01 = 0.f, v23 = 0.f;
            #pragma unroll
            for (int i = 0; i < 16; i++) { v01 += s[i]; v23 += s[16 + i]; }
            float* g = arr ? g_posp : g_negp;
            g[(size_t)(j0 + col) * NT + 2 * bi]     = v01;
            g[(size_t)(j0 + col) * NT + 2 * bi + 1] = v23;
        }
    }
}

// Per-row loss + fused final reduction (last-block pattern, deterministic).
__global__ void k_row(const int* __restrict__ lab, float* __restrict__ out) {
    int g = blockIdx.x * 256 + threadIdx.x;
    int row = g >> 4, sub = g & 15;
    const float4* np = (const float4*)&g_negp[(size_t)row * NT + sub * 8];
    const float4* pp = (const float4*)&g_posp[(size_t)row * NT + sub * 8];
    float neg = 0.f, pos = 0.f;
    #pragma unroll
    for (int q = 0; q < 2; q++) {
        float4 a = np[q], b = pp[q];
        neg += (a.x + a.y) + (a.z + a.w);
        pos += (b.x + b.y) + (b.z + b.w);
    }
    #pragma unroll
    for (int o = 1; o < 16; o <<= 1) {
        neg += __shfl_xor_sync(0xffffffffu, neg, o);
        pos += __shfl_xor_sync(0xffffffffu, pos, o);
    }
    __shared__ float sl[16];
    __shared__ int slast;
    if (sub == 0) {
        float self = ex2f(EXSCALE);   // exp(1/T): diagonal term
        int cnt = g_cnt[lab[row] & (NCLS - 1)] - 1;
        sl[threadIdx.x >> 4] = logf(neg - self) - logf((pos - self) / (float)cnt);
    }
    __syncthreads();
    if (threadIdx.x < 16) {
        float l = sl[threadIdx.x];
        #pragma unroll
        for (int o = 8; o > 0; o >>= 1) l += __shfl_xor_sync(0xffffu, l, o);
        if (threadIdx.x == 0) g_bsum[blockIdx.x] = l;
    }
    // Last block performs the deterministic final sum.
    __threadfence();
    if (threadIdx.x == 0) slast = (atomicAdd(&g_done, 1) == RBLK - 1);
    __syncthreads();
    if (slast) {
        int t = threadIdx.x;
        float v = g_bsum[t] + g_bsum[t + 256];
        #pragma unroll
        for (int o = 16; o > 0; o >>= 1) v += __shfl_xor_sync(0xffffffffu, v, o);
        __shared__ float s2[8];
        if ((t & 31) == 0) s2[t >> 5] = v;
        __syncthreads();
        if (t == 0) {
            float s = 0.f;
            #pragma unroll
            for (int i = 0; i < 8; i++) s += s2[i];
            out[0] = s / (float)N_ROWS;
            g_done = 0;   // reset for next graph replay
        }
    }
}

extern "C" void kernel_launch(void* const* d_in, const int* in_sizes, int n_in,
                              void* d_out, int out_size) {
    const float* x   = (const float*)d_in[0];
    const int*   lab = (const int*)d_in[1];
    if (n_in >= 2 && in_sizes[0] < in_sizes[1]) {
        x   = (const float*)d_in[1];
        lab = (const int*)d_in[0];
    }
    float* out = (float*)d_out;

    size_t smem = (size_t)2 * TI * SROW * sizeof(__nv_bfloat16) + 2 * TI * sizeof(int);
    cudaFuncSetAttribute(k_pair, cudaFuncAttributeMaxDynamicSharedMemorySize, (int)smem);

    k_init<<<1, 64>>>();
    k_norm<<<N_ROWS / 8, 256>>>(x, lab);
    k_pair<<<GRID_P, 256, smem>>>(lab);
    k_row<<<RBLK, 256>>>(lab, out);
}

// round 13
// speedup vs baseline: 1.0778x; 1.0778x over previous
#include <cuda_runtime.h>
#include <cuda_fp8.h>
#include <cstdint>

#define N_ROWS 8192
#define DIM    128
#define NCLS   64
#define TI     128                 // CTA tile (M = N = 128)
#define NBI    (N_ROWS / TI)       // 64
#define NT     (NBI * 2)           // 128 partial slots per row
#define NTILES (NBI * (NBI + 1) / 2)   // 2080 upper-tri tiles
#define SROWB  144                 // padded smem row stride in BYTES (128 data + 16)
#define CPAD   33                  // scol contributor stride (pad vs 32)
#define RBLK   512                 // k_row blocks

// ---- scratch (__device__ globals; no cudaMalloc allowed) ----
__device__ uint8_t g_x8[(size_t)N_ROWS * DIM];     // normalized*sqrt(EXSCALE), e4m3
__device__ float g_negp[(size_t)N_ROWS * NT];      // [row][slot]
__device__ float g_posp[(size_t)N_ROWS * NT];
__device__ int   g_cnt[NCLS];
__device__ float g_bsum[RBLK];
__device__ int   g_done;                           // zero-init; reset each call

#define EXSCALE  2.8853900817779268f   // log2(e)/T, T=0.5
#define SQRT_EXS 1.6986436490789138f   // sqrt(EXSCALE)

__device__ __forceinline__ uint32_t smem_u32(const void* p) {
    uint32_t a;
    asm("{ .reg .u64 t; cvta.to.shared.u64 t, %1; cvt.u32.u64 %0, t; }" : "=r"(a) : "l"(p));
    return a;
}
__device__ __forceinline__ float ex2f(float x) {
    float r; asm("ex2.approx.f32 %0, %1;" : "=f"(r) : "f"(x)); return r;
}
__device__ __forceinline__ void ldsm4(uint32_t* r, uint32_t addr) {
    asm volatile("ldmatrix.sync.aligned.m8n8.x4.shared.b16 {%0,%1,%2,%3}, [%4];"
                 : "=r"(r[0]), "=r"(r[1]), "=r"(r[2]), "=r"(r[3]) : "r"(addr));
}
// fp8 e4m3 MMA, fp32 accumulate. Same reg shape as bf16 16816.
__device__ __forceinline__ void mma16832(float* d, const uint32_t* a,
                                         uint32_t b0, uint32_t b1) {
    asm volatile(
        "mma.sync.aligned.m16n8k32.row.col.f32.e4m3.e4m3.f32 "
        "{%0,%1,%2,%3}, {%4,%5,%6,%7}, {%8,%9}, {%0,%1,%2,%3};"
        : "+f"(d[0]), "+f"(d[1]), "+f"(d[2]), "+f"(d[3])
        : "r"(a[0]), "r"(a[1]), "r"(a[2]), "r"(a[3]), "r"(b0), "r"(b1));
}

__global__ void k_init() {
    if (threadIdx.x < NCLS) g_cnt[threadIdx.x] = 0;
}

// One warp per row: float4 load, shfl reduce, e4m3x4 store.
// Label histogram via integer global atomics (deterministic).
__global__ void k_norm(const float* __restrict__ x,
                       const int* __restrict__ lab) {
    int wid  = (blockIdx.x * 256 + threadIdx.x) >> 5;   // global warp = row
    int lane = threadIdx.x & 31;
    float4 v = *(const float4*)&x[(size_t)wid * DIM + lane * 4];
    float ss = v.x * v.x + v.y * v.y + v.z * v.z + v.w * v.w;
    #pragma unroll
    for (int o = 16; o > 0; o >>= 1) ss += __shfl_xor_sync(0xffffffffu, ss, o);
    float sc = SQRT_EXS / fmaxf(sqrtf(ss), 1e-12f);
    __nv_fp8x2_storage_t lo = __nv_cvt_float2_to_fp8x2(
        make_float2(v.x * sc, v.y * sc), __NV_SATFINITE, __NV_E4M3);
    __nv_fp8x2_storage_t hi = __nv_cvt_float2_to_fp8x2(
        make_float2(v.z * sc, v.w * sc), __NV_SATFINITE, __NV_E4M3);
    uint32_t packed = (uint32_t)lo | ((uint32_t)hi << 16);
    *(uint32_t*)&g_x8[(size_t)wid * DIM + lane * 4] = packed;
    if (lane == 0) atomicAdd(&g_cnt[lab[wid] & (NCLS - 1)], 1);
}

// Upper-triangular 128x128 Gram tile (bi <= bj), fp8 tensor cores.
// Row-side partials (slots 2*bj+warp_n) + column-side (slots 2*bi+{0,1}).
__global__ void __launch_bounds__(256, 2)
k_pair(const int* __restrict__ lab) {
    extern __shared__ char sm[];
    char* As = sm;                                     // [128][SROWB] bytes
    char* Bs = sm + TI * SROWB;                        // [128][SROWB]
    int* labJ = (int*)(Bs + TI * SROWB);               // [128]
    int* labI = labJ + TI;                             // [128]
    float* scol = (float*)sm;                          // reused post-MMA: [2][128][CPAD]

    int tid  = threadIdx.x;
    int w    = tid >> 5;
    int lane = tid & 31;

    // 1D triangular mapping: t = bj*(bj+1)/2 + bi, bi <= bj.
    int t4 = blockIdx.x;
    int bj = (int)((sqrt(8.0 * (double)t4 + 1.0) - 1.0) * 0.5);
    int bi = t4 - bj * (bj + 1) / 2;
    int i0 = bi * TI;
    int j0 = bj * TI;

    // Cooperative tile load: 16B chunks (8 chunks per 128B row).
    #pragma unroll
    for (int it = 0; it < 8; it++) {
        int idx = tid + it * 256;           // 0..2047
        int sub = idx >> 10;                // 0 = A(i), 1 = B(j)
        int loc = idx & 1023;
        int row = loc >> 3, c = loc & 7;
        int grow = (sub ? j0 : i0) + row;
        uint4 v = *(const uint4*)&g_x8[(size_t)grow * DIM + c * 16];
        char* dst = sub ? Bs : As;
        *(uint4*)(dst + row * SROWB + c * 16) = v;
    }
    if (tid < TI) labJ[tid] = lab[j0 + tid];
    else          labI[tid - TI] = lab[i0 + tid - TI];
    __syncthreads();

    int warp_m = w >> 1;                    // 0..3  -> 32-row slab
    int warp_n = w & 1;                     // 0..1  -> 64-col half
    uint32_t asb = smem_u32(As), bsb = smem_u32(Bs);

    // ldmatrix b16-view of fp8 pairs. A x4: (m0-7,B0-15),(m8-15,B0-15),
    // (m0-7,B16-31),(m8-15,B16-31) -> exactly the a0..a3 of m16n8k32.
    uint32_t a_row = (uint32_t)(warp_m * 32 + (lane & 7) + ((lane >> 3) & 1) * 8);
    uint32_t aaddr = asb + a_row * SROWB + ((lane >> 4) * 16);
    // B x4: (n-grp0,B0-15),(n-grp0,B16-31),(n-grp1,B0-15),(n-grp1,B16-31)
    uint32_t b_n = (uint32_t)(warp_n * 64 + ((lane >> 4) << 3) + (lane & 7));
    uint32_t baddr = bsb + b_n * SROWB + (((lane >> 3) & 1) * 16);

    float acc[2][8][4];
    #pragma unroll
    for (int mf = 0; mf < 2; mf++)
        #pragma unroll
        for (int nf = 0; nf < 8; nf++)
            #pragma unroll
            for (int e = 0; e < 4; e++) acc[mf][nf][e] = 0.0f;

    #pragma unroll
    for (int ks = 0; ks < 4; ks++) {       // k32 per step, 4 steps = K128
        uint32_t a[2][4], b[4][4];
        ldsm4(a[0], aaddr + ks * 32);
        ldsm4(a[1], aaddr + 16 * SROWB + ks * 32);
        #pragma unroll
        for (int q = 0; q < 4; q++)
            ldsm4(b[q], baddr + q * 16 * SROWB + ks * 32);
        #pragma unroll
        for (int mf = 0; mf < 2; mf++)
            #pragma unroll
            for (int nf = 0; nf < 8; nf++)
                mma16832(acc[mf][nf], a[mf], b[nf >> 1][(nf & 1) * 2],
                         b[nf >> 1][(nf & 1) * 2 + 1]);
    }

    int lj[8][2];
    #pragma unroll
    for (int nf = 0; nf < 8; nf++) {
        int j = warp_n * 64 + nf * 8 + ((lane & 3) << 1);
        lj[nf][0] = labJ[j];
        lj[nf][1] = labJ[j + 1];
    }
    int li4[2][2];
    #pragma unroll
    for (int mf = 0; mf < 2; mf++)
        #pragma unroll
        for (int rh = 0; rh < 2; rh++)
            li4[mf][rh] = labI[warp_m * 32 + mf * 16 + (lane >> 2) + rh * 8];
    __syncthreads();   // labels consumed; smem reused as scol

    float colneg[8][2], colpos[8][2];
    #pragma unroll
    for (int nf = 0; nf < 8; nf++)
        colneg[nf][0] = colneg[nf][1] = colpos[nf][0] = colpos[nf][1] = 0.0f;

    // acc = dot*EXSCALE (folded into quantized vectors) -> ex2 directly.
    #pragma unroll
    for (int mf = 0; mf < 2; mf++) {
        #pragma unroll
        for (int rh = 0; rh < 2; rh++) {
            int li = li4[mf][rh];
            float neg = 0.0f, pos = 0.0f;
            #pragma unroll
            for (int nf = 0; nf < 8; nf++) {
                float s0 = ex2f(acc[mf][nf][2 * rh]);
                float s1 = ex2f(acc[mf][nf][2 * rh + 1]);
                neg += s0 + s1;
                colneg[nf][0] += s0;
                colneg[nf][1] += s1;
                if (li == lj[nf][0]) { pos += s0; colpos[nf][0] += s0; }
                if (li == lj[nf][1]) { pos += s1; colpos[nf][1] += s1; }
            }
            neg += __shfl_xor_sync(0xffffffffu, neg, 1);
            neg += __shfl_xor_sync(0xffffffffu, neg, 2);
            pos += __shfl_xor_sync(0xffffffffu, pos, 1);
            pos += __shfl_xor_sync(0xffffffffu, pos, 2);
            if ((lane & 3) == 0) {
                int grow = i0 + warp_m * 32 + mf * 16 + (lane >> 2) + rh * 8;
                g_negp[(size_t)grow * NT + 2 * bj + warp_n] = neg;
                g_posp[(size_t)grow * NT + 2 * bj + warp_n] = pos;
            }
        }
    }

    // Column-side smem transpose-reduce.
    {
        int contrib = warp_m * 8 + (lane >> 2);
        #pragma unroll
        for (int nf = 0; nf < 8; nf++) {
            int col = warp_n * 64 + nf * 8 + ((lane & 3) << 1);
            scol[(col)           * CPAD + contrib] = colneg[nf][0];
            scol[(col + 1)       * CPAD + contrib] = colneg[nf][1];
            scol[(128 + col)     * CPAD + contrib] = colpos[nf][0];
            scol[(128 + col + 1) * CPAD + contrib] = colpos[nf][1];
        }
    }
    __syncthreads();

    if (bi != bj) {
        int col = tid & 127, arr = tid >> 7;   // 0 = neg, 1 = pos
        const float* s = scol + (arr * 128 + col) * CPAD;
        float v01 = 0.f, v23 = 0.f;
        #pragma unroll
        for (int i = 0; i < 16; i++) { v01 += s[i]; v23 += s[16 + i]; }
        float* g = arr ? g_posp : g_negp;
        g[(size_t)(j0 + col) * NT + 2 * bi]     = v01;
        g[(size_t)(j0 + col) * NT + 2 * bi + 1] = v23;
    }
}

// Per-row loss + fused final reduction (last-block pattern, deterministic).
__global__ void k_row(const int* __restrict__ lab, float* __restrict__ out) {
    int g = blockIdx.x * 256 + threadIdx.x;
    int row = g >> 4, sub = g & 15;
    const float4* np = (const float4*)&g_negp[(size_t)row * NT + sub * 8];
    const float4* pp = (const float4*)&g_posp[(size_t)row * NT + sub * 8];
    float neg = 0.f, pos = 0.f;
    #pragma unroll
    for (int q = 0; q < 2; q++) {
        float4 a = np[q], b = pp[q];
        neg += (a.x + a.y) + (a.z + a.w);
        pos += (b.x + b.y) + (b.z + b.w);
    }
    #pragma unroll
    for (int o = 1; o < 16; o <<= 1) {
        neg += __shfl_xor_sync(0xffffffffu, neg, o);
        pos += __shfl_xor_sync(0xffffffffu, pos, o);
    }
    __shared__ float sl[16];
    __shared__ int slast;
    if (sub == 0) {
        float self = ex2f(EXSCALE);   // exp(1/T): diagonal term
        int cnt = g_cnt[lab[row] & (NCLS - 1)] - 1;
        sl[threadIdx.x >> 4] = logf(neg - self) - logf((pos - self) / (float)cnt);
    }
    __syncthreads();
    if (threadIdx.x < 16) {
        float l = sl[threadIdx.x];
        #pragma unroll
        for (int o = 8; o > 0; o >>= 1) l += __shfl_xor_sync(0xffffu, l, o);
        if (threadIdx.x == 0) g_bsum[blockIdx.x] = l;
    }
    __threadfence();
    if (threadIdx.x == 0) slast = (atomicAdd(&g_done, 1) == RBLK - 1);
    __syncthreads();
    if (slast) {
        int t = threadIdx.x;
        float v = g_bsum[t] + g_bsum[t + 256];
        #pragma unroll
        for (int o = 16; o > 0; o >>= 1) v += __shfl_xor_sync(0xffffffffu, v, o);
        __shared__ float s2[8];
        if ((t & 31) == 0) s2[t >> 5] = v;
        __syncthreads();
        if (t == 0) {
            float s = 0.f;
            #pragma unroll
            for (int i = 0; i < 8; i++) s += s2[i];
            out[0] = s / (float)N_ROWS;
            g_done = 0;   // reset for next graph replay
        }
    }
}

extern "C" void kernel_launch(void* const* d_in, const int* in_sizes, int n_in,
                              void* d_out, int out_size) {
    const float* x   = (const float*)d_in[0];
    const int*   lab = (const int*)d_in[1];
    if (n_in >= 2 && in_sizes[0] < in_sizes[1]) {
        x   = (const float*)d_in[1];
        lab = (const int*)d_in[0];
    }
    float* out = (float*)d_out;

    // smem: two byte tiles + labels (scol reuses the same region afterwards)
    size_t smem = (size_t)2 * TI * SROWB + 2 * TI * sizeof(int);
    size_t scolb = (size_t)2 * 128 * CPAD * sizeof(float);
    if (scolb > smem) smem = scolb;
    cudaFuncSetAttribute(k_pair, cudaFuncAttributeMaxDynamicSharedMemorySize, (int)smem);

    k_init<<<1, 64>>>();
    k_norm<<<N_ROWS / 8, 256>>>(x, lab);
    k_pair<<<NTILES, 256, smem>>>(lab);
    k_row<<<RBLK, 256>>>(lab, out);
}